// round 15
// baseline (speedup 1.0000x reference)
#include <cuda_runtime.h>

#define NB     11
#define NBINS  1331        // 11^3
#define NBPAD  1332        // padded so flush pairs divide evenly
#define ITER   20
#define TPB    128         // 4 warps per block
#define NWARP  4
#define WHB    (NBPAD * 8) // bytes per warp-private histogram (u8, 8 copies)
#define NGC    8           // global histogram copies
#define CHUNK  60          // u8 flush period: max +4/iter/copy -> 240 <= 255; %5==0

__device__ int          g_histG[NGC][NBINS];  // zero-init; re-zeroed by last block
__device__ unsigned int g_done;               // zero-init; reset by last block

// Predicated compare-accumulate, -W folded into the selp constants:
//   acc = selp(x>c0, 0, 10W) + sum_{j=1..9} W*(x > c_j)  ==  W*((iv-1) mod 11)
#define CHAN_ACC(acc, xx, c, WS, W10S)                                         \
    asm("{\n\t"                                                                \
        ".reg .pred p;\n\t"                                                    \
        "setp.gt.f32 p, %1, %2;\n\t"                                           \
        "selp.b32 %0, 0, " W10S ", p;\n\t"                                     \
        "setp.gt.f32 p, %1, %3;\n\t@p add.s32 %0, %0, " WS ";\n\t"             \
        "setp.gt.f32 p, %1, %4;\n\t@p add.s32 %0, %0, " WS ";\n\t"             \
        "setp.gt.f32 p, %1, %5;\n\t@p add.s32 %0, %0, " WS ";\n\t"             \
        "setp.gt.f32 p, %1, %6;\n\t@p add.s32 %0, %0, " WS ";\n\t"             \
        "setp.gt.f32 p, %1, %7;\n\t@p add.s32 %0, %0, " WS ";\n\t"             \
        "setp.gt.f32 p, %1, %8;\n\t@p add.s32 %0, %0, " WS ";\n\t"             \
        "setp.gt.f32 p, %1, %9;\n\t@p add.s32 %0, %0, " WS ";\n\t"             \
        "setp.gt.f32 p, %1, %10;\n\t@p add.s32 %0, %0, " WS ";\n\t"            \
        "setp.gt.f32 p, %1, %11;\n\t@p add.s32 %0, %0, " WS ";\n\t"            \
        "}"                                                                    \
        : "=r"(acc)                                                            \
        : "f"(xx), "f"((c)[0]), "f"((c)[1]), "f"((c)[2]), "f"((c)[3]),         \
          "f"((c)[4]), "f"((c)[5]), "f"((c)[6]), "f"((c)[7]), "f"((c)[8]),     \
          "f"((c)[9]))

// Branchless deposit (proven R12/R14): 3 butterfly shuffles dedup the 4-lane
// copy-group; leader adds group count via predicated LDS/STS. No "memory"
// clobber: deposits only touch smem inside asm, and all C++ accesses to wh
// are separated from deposits by __syncthreads() — lets the compiler batch
// the global loads across deposits (MLP).
__device__ __forceinline__ void deposit_bl(unsigned addr, int bin,
                                           int l1, int l2, int l3, int inval) {
    asm volatile(
        "{\n\t"
        ".reg .pred p8, p16, p24, pl;\n\t"
        ".reg .u32 b8, b16, b24, a, bad, v;\n\t"
        "shfl.sync.bfly.b32 b8,  %1, 8,  0x1f, 0xffffffff;\n\t"
        "shfl.sync.bfly.b32 b16, %1, 16, 0x1f, 0xffffffff;\n\t"
        "shfl.sync.bfly.b32 b24, %1, 24, 0x1f, 0xffffffff;\n\t"
        "setp.eq.s32 p8,  %1, b8;\n\t"
        "setp.eq.s32 p16, %1, b16;\n\t"
        "setp.eq.s32 p24, %1, b24;\n\t"
        "mov.u32 a, 1;\n\t"
        "@p8  add.u32 a, a, 1;\n\t"
        "@p16 add.u32 a, a, 1;\n\t"
        "@p24 add.u32 a, a, 1;\n\t"
        "mov.u32 bad, %5;\n\t"
        "@p8  or.b32 bad, bad, %2;\n\t"
        "@p16 or.b32 bad, bad, %3;\n\t"
        "@p24 or.b32 bad, bad, %4;\n\t"
        "setp.eq.u32 pl, bad, 0;\n\t"
        "@pl ld.shared.u8 v, [%0];\n\t"
        "@pl add.u32 v, v, a;\n\t"
        "@pl st.shared.u8 [%0], v;\n\t"
        "}"
        :: "r"(addr), "r"(bin), "r"(l1), "r"(l2), "r"(l3), "r"(inval));
}

__global__ void __launch_bounds__(TPB, 5) fused_kernel(
    const float4* __restrict__ x, int n, int full, int stride,
    const float*  __restrict__ r_cut,
    const float*  __restrict__ g_cut,
    const float*  __restrict__ b_cut,
    float* __restrict__ out)
{
    __shared__ __align__(16) unsigned char wh[NWARP * WHB];   // 42624 B
    __shared__ float s_cut255[3][NB];
    __shared__ float s_cut01[3][NB];
    __shared__ unsigned long long s_wmax[NWARP];
    __shared__ int s_top[ITER];
    __shared__ int s_last;

    const int tid  = threadIdx.x;
    const int lane = tid & 31;
    const int wid  = tid >> 5;

    // ---- cuts: clip + rank-sort (clip/sort commute; stable ties by index) ----
    if (tid < 33) {
        int c = tid / NB, j = tid - c * NB;
        const float* src = (c == 0) ? r_cut : (c == 1) ? g_cut : b_cut;
        float vj = fminf(fmaxf(src[j], 0.0f), 1.0f);
        int rank = 0;
        for (int k = 0; k < NB; k++) {
            float vk = fminf(fmaxf(src[k], 0.0f), 1.0f);
            rank += (vk < vj) || (vk == vj && k < j);
        }
        s_cut01[c][rank] = vj;
    }
    {   // zero private histograms (incl. pad bin)
        uint4* w4 = (uint4*)wh;
        for (int i = tid; i < (NWARP * WHB) / 16; i += TPB) w4[i] = make_uint4(0u, 0u, 0u, 0u);
    }
    __syncthreads();
    if (tid < 33) {
        int c = tid / NB, j = tid - c * NB;
        float v = s_cut01[c][j];
        if (j == 0)      v = 0.0f;
        if (j == NB - 1) v = 1.0f;
        s_cut01[c][j]  = v;
        s_cut255[c][j] = v * 255.0f;
    }
    __syncthreads();

    // cut[10]*255 == 255 > x always (x = u*255, u<1) -> only j=0..9 compare.
    float rc[NB - 1], gc[NB - 1], bc[NB - 1];
#pragma unroll
    for (int i = 0; i < NB - 1; i++) {
        rc[i] = s_cut255[0][i];
        gc[i] = s_cut255[1][i];
        bc[i] = s_cut255[2][i];
    }

    const int copy = lane & 7;
    const int q    = lane >> 3;
    const int l1   = ((q ^ 1) < q) ? 1 : 0;
    const int l2   = ((q ^ 2) < q) ? 1 : 0;
    const int l3   = ((q ^ 3) < q) ? 1 : 0;

    unsigned whbase;
    asm("{ .reg .u64 t; cvta.to.shared.u64 t, %1; cvt.u32.u64 %0, t; }"
        : "=r"(whbase) : "l"(wh));
    const unsigned myhc = whbase + (unsigned)(wid * WHB + copy);

    const int gtid = blockIdx.x * TPB + tid;
    int* gdst = g_histG[blockIdx.x & (NGC - 1)];

#define BIN_OF(p, bin) do {                                                    \
        int accR, accG, accB;                                                  \
        CHAN_ACC(accR, (p).x, rc, "121", "1210");                              \
        CHAN_ACC(accG, (p).y, gc, "11",  "110");                               \
        CHAN_ACC(accB, (p).z, bc, "1",   "10");                                \
        (bin) = accR + accG + accB;                                            \
    } while (0)

    // block-level flush, 2 bins per thread per round via uint4 (16B = 2 bins
    // x 8 copies per warp); dp4a-merge all 4 warps, zero in place, one ATOMG
    // per nonzero bin. Pair 665 covers bins {1330, 1331}; pad bin 1331 is
    // always zero so its atom is skipped by the s1 predicate.
#define FLUSH() do {                                                           \
        __syncthreads();                                                       \
        for (int _p = tid; _p < NBPAD / 2; _p += TPB) {                        \
            unsigned _s0 = 0, _s1 = 0;                                         \
            _Pragma("unroll")                                                  \
            for (int _w = 0; _w < NWARP; _w++) {                               \
                uint4* _wp = (uint4*)(wh + _w * WHB + _p * 16);                \
                uint4 _v = *_wp;                                               \
                *_wp = make_uint4(0u, 0u, 0u, 0u);                             \
                _s0 = __dp4a(_v.x, 0x01010101u,                                \
                      __dp4a(_v.y, 0x01010101u, _s0));                         \
                _s1 = __dp4a(_v.z, 0x01010101u,                                \
                      __dp4a(_v.w, 0x01010101u, _s1));                         \
            }                                                                  \
            if (_s0) atomicAdd(&gdst[2 * _p], (int)_s0);                       \
            if (_s1) atomicAdd(&gdst[2 * _p + 1], (int)_s1);                   \
        }                                                                      \
        __syncthreads();                                                       \
    } while (0)

    // ---- main loop: CHUNK iterations per flush; batches of 5 with all five
    // LDGs issued up-front (MLP=5), then bins, then deposits ----
    int r = 0;
    while (r < full) {
        int end = min(r + CHUNK, full);
        for (; r + 5 <= end; r += 5) {
            float4 p0 = __ldcs(&x[gtid + (r + 0) * stride]);
            float4 p1 = __ldcs(&x[gtid + (r + 1) * stride]);
            float4 p2 = __ldcs(&x[gtid + (r + 2) * stride]);
            float4 p3 = __ldcs(&x[gtid + (r + 3) * stride]);
            float4 p4 = __ldcs(&x[gtid + (r + 4) * stride]);
            int b0, b1, b2, b3, b4;
            BIN_OF(p0, b0);
            BIN_OF(p1, b1);
            BIN_OF(p2, b2);
            BIN_OF(p3, b3);
            BIN_OF(p4, b4);
            deposit_bl(myhc + ((unsigned)b0 << 3), b0, l1, l2, l3, 0);
            deposit_bl(myhc + ((unsigned)b1 << 3), b1, l1, l2, l3, 0);
            deposit_bl(myhc + ((unsigned)b2 << 3), b2, l1, l2, l3, 0);
            deposit_bl(myhc + ((unsigned)b3 << 3), b3, l1, l2, l3, 0);
            deposit_bl(myhc + ((unsigned)b4 << 3), b4, l1, l2, l3, 0);
        }
        for (; r < end; r++) {
            float4 p = __ldcs(&x[gtid + r * stride]);
            int bin;
            BIN_OF(p, bin);
            deposit_bl(myhc + ((unsigned)bin << 3), bin, l1, l2, l3, 0);
        }
        FLUSH();
    }
    // guarded tail round (hist freshly zeroed; adds <= 4 per copy)
    {
        int idx = gtid + full * stride;
        bool valid = idx < n;
        int bin = -1 - lane;            // unique per lane -> no false match
        if (valid) {
            float4 p = __ldcs(&x[idx]);
            BIN_OF(p, bin);
        }
        unsigned a = myhc + ((unsigned)(valid ? bin : 0) << 3);
        deposit_bl(a, bin, l1, l2, l3, valid ? 0 : 1);
        FLUSH();
    }

    // ---- ticket: last block does the top-k ----
    __threadfence();
    if (tid == 0) s_last = (atomicAdd(&g_done, 1u) == (unsigned)gridDim.x - 1u);
    __syncthreads();
    if (!s_last) return;
    __threadfence();

    unsigned long long* keys = (unsigned long long*)wh;   // 10648 B, fits
    for (int i = tid; i < NBINS; i += TPB) {
        unsigned int c = 0;
#pragma unroll
        for (int k = 0; k < NGC; k++) c += (unsigned int)__ldcg(&g_histG[k][i]);
        keys[i] = (((unsigned long long)c << 11) |
                   (unsigned long long)(1330 - i)) + 1ull;
#pragma unroll
        for (int k = 0; k < NGC; k++) g_histG[k][i] = 0;   // reset for replay
    }
    __syncthreads();

    for (int it = 0; it < ITER; it++) {
        unsigned long long m = 0;
        for (int i = tid; i < NBINS; i += TPB) {
            unsigned long long k = keys[i];
            m = (k > m) ? k : m;
        }
#pragma unroll
        for (int o = 16; o > 0; o >>= 1) {
            unsigned long long k = __shfl_xor_sync(0xffffffffu, m, o);
            m = (k > m) ? k : m;
        }
        if (lane == 0) s_wmax[wid] = m;
        __syncthreads();
        if (tid == 0) {
            unsigned long long w = 0;
#pragma unroll
            for (int k = 0; k < NWARP; k++) w = (s_wmax[k] > w) ? s_wmax[k] : w;
            int bin = 1330 - (int)((w - 1ull) & 0x7FFull);
            s_top[it] = bin;
            keys[bin] = 0ull;
        }
        __syncthreads();
    }

    if (tid < ITER) {
        int bin = s_top[tid];
        int r2 = bin / 121;
        int g2 = (bin / 11) % 11;
        int b2 = bin % 11;
        r2 = min(r2, NB - 2);
        g2 = min(g2, NB - 2);
        b2 = min(b2, NB - 2);
        float rv = 255.0f * (float)r2 / (float)NB + (s_cut01[0][r2 + 1] - s_cut01[0][r2]) * 255.0f / 2.0f;
        float gv = 255.0f * (float)g2 / (float)NB + (s_cut01[1][g2 + 1] - s_cut01[1][g2]) * 255.0f / 2.0f;
        float bv = 255.0f * (float)b2 / (float)NB + (s_cut01[2][b2 + 1] - s_cut01[2][b2]) * 255.0f / 2.0f;
        out[tid * 4 + 0] = rv;
        out[tid * 4 + 1] = gv;
        out[tid * 4 + 2] = bv;
        out[tid * 4 + 3] = 255.0f;
    }
    if (tid == 0) g_done = 0;   // reset ticket for next replay
}

// ---------------------------------------------------------------------------
extern "C" void kernel_launch(void* const* d_in, const int* in_sizes, int n_in,
                              void* d_out, int out_size) {
    const float* x  = (const float*)d_in[0];
    const float* rc = (const float*)d_in[1];
    const float* gc = (const float*)d_in[2];
    const float* bc = (const float*)d_in[3];
    int n = in_sizes[0] / 4;   // number of pixels

    // size grid to exactly one resident wave (host-side, capture-safe)
    int dev = 0, sms = 148, occ = 5;
    cudaGetDevice(&dev);
    cudaDeviceGetAttribute(&sms, cudaDevAttrMultiProcessorCount, dev);
    cudaOccupancyMaxActiveBlocksPerMultiprocessor(&occ, fused_kernel, TPB, 0);
    if (occ < 1) occ = 1;
    int grid   = sms * occ;
    int stride = grid * TPB;
    int full   = n / stride;

    fused_kernel<<<grid, TPB>>>((const float4*)x, n, full, stride,
                                rc, gc, bc, (float*)d_out);
}

// round 16
// speedup vs baseline: 1.1701x; 1.1701x over previous
#include <cuda_runtime.h>

#define NB     11
#define NBINS  1331        // 11^3
#define ITER   20
#define TPB    128         // 4 warps per block
#define NWARP  4
#define WHB    (NBINS * 8) // bytes per warp-private histogram (u8, 8 copies)
#define NGC    8           // global histogram copies
#define CHUNK  60          // u8 flush period: max +4/iter/copy -> 240 <= 255; %4==0

__device__ int          g_histG[NGC][NBINS];  // zero-init; re-zeroed by last block
__device__ unsigned int g_done;               // zero-init; reset by last block

// Predicated compare-accumulate, -W folded into the selp constants:
//   acc = selp(x>c0, 0, 10W) + sum_{j=1..9} W*(x > c_j)  ==  W*((iv-1) mod 11)
#define CHAN_ACC(acc, xx, c, WS, W10S)                                         \
    asm("{\n\t"                                                                \
        ".reg .pred p;\n\t"                                                    \
        "setp.gt.f32 p, %1, %2;\n\t"                                           \
        "selp.b32 %0, 0, " W10S ", p;\n\t"                                     \
        "setp.gt.f32 p, %1, %3;\n\t@p add.s32 %0, %0, " WS ";\n\t"             \
        "setp.gt.f32 p, %1, %4;\n\t@p add.s32 %0, %0, " WS ";\n\t"             \
        "setp.gt.f32 p, %1, %5;\n\t@p add.s32 %0, %0, " WS ";\n\t"             \
        "setp.gt.f32 p, %1, %6;\n\t@p add.s32 %0, %0, " WS ";\n\t"             \
        "setp.gt.f32 p, %1, %7;\n\t@p add.s32 %0, %0, " WS ";\n\t"             \
        "setp.gt.f32 p, %1, %8;\n\t@p add.s32 %0, %0, " WS ";\n\t"             \
        "setp.gt.f32 p, %1, %9;\n\t@p add.s32 %0, %0, " WS ";\n\t"             \
        "setp.gt.f32 p, %1, %10;\n\t@p add.s32 %0, %0, " WS ";\n\t"            \
        "setp.gt.f32 p, %1, %11;\n\t@p add.s32 %0, %0, " WS ";\n\t"            \
        "}"                                                                    \
        : "=r"(acc)                                                            \
        : "f"(xx), "f"((c)[0]), "f"((c)[1]), "f"((c)[2]), "f"((c)[3]),         \
          "f"((c)[4]), "f"((c)[5]), "f"((c)[6]), "f"((c)[7]), "f"((c)[8]),     \
          "f"((c)[9]))

// Deposit phase A: issue the 3 dedup shuffles and the UNCONDITIONAL u8 load.
// Results are consumed ~67 slots later (after the next pixel's compare chain),
// so SHFL (26cyc) and LDS (29cyc) latencies are fully hidden.
__device__ __forceinline__ void depA(unsigned addr, int bin,
                                     int& b8, int& b16, int& b24, unsigned& v) {
    asm volatile(
        "shfl.sync.bfly.b32 %0, %4, 8, 0x1f, 0xffffffff;\n\t"
        "shfl.sync.bfly.b32 %1, %4, 16, 0x1f, 0xffffffff;\n\t"
        "shfl.sync.bfly.b32 %2, %4, 24, 0x1f, 0xffffffff;\n\t"
        "ld.shared.u8 %3, [%5];"
        : "=r"(b8), "=r"(b16), "=r"(b24), "=r"(v)
        : "r"(bin), "r"(addr));
}

// Deposit phase B: leader's predicated store of the updated count.
__device__ __forceinline__ void depB(unsigned addr, unsigned t, int bad) {
    asm volatile(
        "{\n\t.reg .pred pl;\n\t"
        "setp.eq.s32 pl, %2, 0;\n\t"
        "@pl st.shared.u8 [%0], %1;\n\t}"
        :: "r"(addr), "r"(t), "r"(bad));
}

// Monolithic branchless deposit (proven R12/R14) — used in the epilogue/tail.
__device__ __forceinline__ void deposit_bl(unsigned addr, int bin,
                                           int l1, int l2, int l3, int inval) {
    asm volatile(
        "{\n\t"
        ".reg .pred p8, p16, p24, pl;\n\t"
        ".reg .u32 b8, b16, b24, a, bad, v;\n\t"
        "shfl.sync.bfly.b32 b8,  %1, 8,  0x1f, 0xffffffff;\n\t"
        "shfl.sync.bfly.b32 b16, %1, 16, 0x1f, 0xffffffff;\n\t"
        "shfl.sync.bfly.b32 b24, %1, 24, 0x1f, 0xffffffff;\n\t"
        "setp.eq.s32 p8,  %1, b8;\n\t"
        "setp.eq.s32 p16, %1, b16;\n\t"
        "setp.eq.s32 p24, %1, b24;\n\t"
        "mov.u32 a, 1;\n\t"
        "@p8  add.u32 a, a, 1;\n\t"
        "@p16 add.u32 a, a, 1;\n\t"
        "@p24 add.u32 a, a, 1;\n\t"
        "mov.u32 bad, %5;\n\t"
        "@p8  or.b32 bad, bad, %2;\n\t"
        "@p16 or.b32 bad, bad, %3;\n\t"
        "@p24 or.b32 bad, bad, %4;\n\t"
        "setp.eq.u32 pl, bad, 0;\n\t"
        "@pl ld.shared.u8 v, [%0];\n\t"
        "@pl add.u32 v, v, a;\n\t"
        "@pl st.shared.u8 [%0], v;\n\t"
        "}"
        :: "r"(addr), "r"(bin), "r"(l1), "r"(l2), "r"(l3), "r"(inval));
}

__global__ void __launch_bounds__(TPB, 5) fused_kernel(
    const float4* __restrict__ x, int n, int full, int stride,
    const float*  __restrict__ r_cut,
    const float*  __restrict__ g_cut,
    const float*  __restrict__ b_cut,
    float* __restrict__ out)
{
    __shared__ __align__(16) unsigned char wh[NWARP * WHB];   // 42592 B
    __shared__ float s_cut255[3][NB];
    __shared__ float s_cut01[3][NB];
    __shared__ unsigned long long s_wmax[NWARP];
    __shared__ int s_top[ITER];
    __shared__ int s_last;

    const int tid  = threadIdx.x;
    const int lane = tid & 31;
    const int wid  = tid >> 5;

    // ---- cuts: clip + rank-sort (clip/sort commute; stable ties by index) ----
    if (tid < 33) {
        int c = tid / NB, j = tid - c * NB;
        const float* src = (c == 0) ? r_cut : (c == 1) ? g_cut : b_cut;
        float vj = fminf(fmaxf(src[j], 0.0f), 1.0f);
        int rank = 0;
        for (int k = 0; k < NB; k++) {
            float vk = fminf(fmaxf(src[k], 0.0f), 1.0f);
            rank += (vk < vj) || (vk == vj && k < j);
        }
        s_cut01[c][rank] = vj;
    }
    {   // zero private histograms
        uint4* w4 = (uint4*)wh;
        for (int i = tid; i < (NWARP * WHB) / 16; i += TPB) w4[i] = make_uint4(0u, 0u, 0u, 0u);
    }
    __syncthreads();
    if (tid < 33) {
        int c = tid / NB, j = tid - c * NB;
        float v = s_cut01[c][j];
        if (j == 0)      v = 0.0f;
        if (j == NB - 1) v = 1.0f;
        s_cut01[c][j]  = v;
        s_cut255[c][j] = v * 255.0f;
    }
    __syncthreads();

    // cut[10]*255 == 255 > x always (x = u*255, u<1) -> only j=0..9 compare.
    float rc[NB - 1], gc[NB - 1], bc[NB - 1];
#pragma unroll
    for (int i = 0; i < NB - 1; i++) {
        rc[i] = s_cut255[0][i];
        gc[i] = s_cut255[1][i];
        bc[i] = s_cut255[2][i];
    }

    const int copy = lane & 7;
    const int q    = lane >> 3;
    const int lq1  = q & 1;            // suppress if matched partner has lower q
    const int lq2  = q & 2;
    const int l1   = lq1;              // for deposit_bl (same semantics)
    const int l2   = lq2 ? 1 : 0;
    const int l3   = l2;

    unsigned whbase;
    asm("{ .reg .u64 t; cvta.to.shared.u64 t, %1; cvt.u32.u64 %0, t; }"
        : "=r"(whbase) : "l"(wh));
    const unsigned myhc = whbase + (unsigned)(wid * WHB + copy);

    const int gtid = blockIdx.x * TPB + tid;
    int* gdst = g_histG[blockIdx.x & (NGC - 1)];

#define BIN_OF(p, bin) do {                                                    \
        int accR, accG, accB;                                                  \
        CHAN_ACC(accR, (p).x, rc, "121", "1210");                              \
        CHAN_ACC(accG, (p).y, gc, "11",  "110");                               \
        CHAN_ACC(accB, (p).z, bc, "1",   "10");                                \
        (bin) = accR + accG + accB;                                            \
    } while (0)

    // block-level flush (proven R14): merge all 4 warp hists per bin (dp4a),
    // one ATOMG per bin per block per pass; zero in place.
#define FLUSH() do {                                                           \
        __syncthreads();                                                       \
        for (int _bin = tid; _bin < NBINS; _bin += TPB) {                      \
            unsigned _s = 0;                                                   \
            _Pragma("unroll")                                                  \
            for (int _w = 0; _w < NWARP; _w++) {                               \
                uint2* _wp = (uint2*)(wh + _w * WHB + _bin * 8);               \
                uint2 _v = *_wp;                                               \
                *_wp = make_uint2(0u, 0u);                                     \
                _s = __dp4a(_v.x, 0x01010101u,                                 \
                     __dp4a(_v.y, 0x01010101u, _s));                           \
            }                                                                  \
            if (_s) atomicAdd(&gdst[_bin], (int)_s);                           \
        }                                                                      \
        __syncthreads();                                                       \
    } while (0)

    // One pipelined step: deposit current bin (A ... chain ... B) while
    // computing the next pixel's bin and refilling the 4-deep prefetch queue.
#define STEP(pc, pn, li) do {                                                  \
        unsigned _addr = myhc + ((unsigned)binc << 3);                         \
        int _b8, _b16, _b24; unsigned _v;                                      \
        depA(_addr, binc, _b8, _b16, _b24, _v);                                \
        (pc) = __ldcs(&x[gtid + (li) * stride]);                               \
        int _binn; BIN_OF((pn), _binn);                                        \
        int _e8  = (binc == _b8);                                              \
        int _e16 = (binc == _b16);                                             \
        int _e24 = (binc == _b24);                                             \
        unsigned _t = _v + (unsigned)(1 + _e8 + _e16 + _e24);                  \
        int _bad = (_e8 & lq1) | ((_e16 | _e24) & lq2);                        \
        depB(_addr, _t, _bad);                                                 \
        binc = _binn;                                                          \
    } while (0)

    // ---- main loop: software-pipelined, prefetch depth 4 ----
    int r = 0;
    const int steady = (full > 4) ? ((full - 4) & ~3) : 0;
    if (steady > 0) {
        float4 p0 = __ldcs(&x[gtid + 0 * stride]);
        float4 p1 = __ldcs(&x[gtid + 1 * stride]);
        float4 p2 = __ldcs(&x[gtid + 2 * stride]);
        float4 p3 = __ldcs(&x[gtid + 3 * stride]);
        int binc;
        BIN_OF(p0, binc);
        while (r < steady) {
            int end = min(r + CHUNK, steady);
            for (; r < end; r += 4) {
                STEP(p0, p1, r + 4);
                STEP(p1, p2, r + 5);
                STEP(p2, p3, r + 6);
                STEP(p3, p0, r + 7);
            }
            FLUSH();
        }
    }
    // ---- epilogue: pixels [steady, full) unpipelined (<= 7) ----
    for (; r < full; r++) {
        float4 p = __ldcs(&x[gtid + r * stride]);
        int bin;
        BIN_OF(p, bin);
        deposit_bl(myhc + ((unsigned)bin << 3), bin, l1, l2 ? 1 : 0, l3, 0);
    }
    // guarded tail round
    {
        int idx = gtid + full * stride;
        bool valid = idx < n;
        int bin = -1 - lane;            // unique per lane -> no false match
        if (valid) {
            float4 p = __ldcs(&x[idx]);
            BIN_OF(p, bin);
        }
        unsigned a = myhc + ((unsigned)(valid ? bin : 0) << 3);
        deposit_bl(a, bin, l1, l2 ? 1 : 0, l3, valid ? 0 : 1);
    }
    FLUSH();

    // ---- ticket: last block does the top-k ----
    __threadfence();
    if (tid == 0) s_last = (atomicAdd(&g_done, 1u) == (unsigned)gridDim.x - 1u);
    __syncthreads();
    if (!s_last) return;
    __threadfence();

    unsigned long long* keys = (unsigned long long*)wh;   // 10648 B, fits
    for (int i = tid; i < NBINS; i += TPB) {
        unsigned int c = 0;
#pragma unroll
        for (int k = 0; k < NGC; k++) c += (unsigned int)__ldcg(&g_histG[k][i]);
        keys[i] = (((unsigned long long)c << 11) |
                   (unsigned long long)(1330 - i)) + 1ull;
#pragma unroll
        for (int k = 0; k < NGC; k++) g_histG[k][i] = 0;   // reset for replay
    }
    __syncthreads();

    for (int it = 0; it < ITER; it++) {
        unsigned long long m = 0;
        for (int i = tid; i < NBINS; i += TPB) {
            unsigned long long k = keys[i];
            m = (k > m) ? k : m;
        }
#pragma unroll
        for (int o = 16; o > 0; o >>= 1) {
            unsigned long long k = __shfl_xor_sync(0xffffffffu, m, o);
            m = (k > m) ? k : m;
        }
        if (lane == 0) s_wmax[wid] = m;
        __syncthreads();
        if (tid == 0) {
            unsigned long long w = 0;
#pragma unroll
            for (int k = 0; k < NWARP; k++) w = (s_wmax[k] > w) ? s_wmax[k] : w;
            int bin = 1330 - (int)((w - 1ull) & 0x7FFull);
            s_top[it] = bin;
            keys[bin] = 0ull;
        }
        __syncthreads();
    }

    if (tid < ITER) {
        int bin = s_top[tid];
        int r2 = bin / 121;
        int g2 = (bin / 11) % 11;
        int b2 = bin % 11;
        r2 = min(r2, NB - 2);
        g2 = min(g2, NB - 2);
        b2 = min(b2, NB - 2);
        float rv = 255.0f * (float)r2 / (float)NB + (s_cut01[0][r2 + 1] - s_cut01[0][r2]) * 255.0f / 2.0f;
        float gv = 255.0f * (float)g2 / (float)NB + (s_cut01[1][g2 + 1] - s_cut01[1][g2]) * 255.0f / 2.0f;
        float bv = 255.0f * (float)b2 / (float)NB + (s_cut01[2][b2 + 1] - s_cut01[2][b2]) * 255.0f / 2.0f;
        out[tid * 4 + 0] = rv;
        out[tid * 4 + 1] = gv;
        out[tid * 4 + 2] = bv;
        out[tid * 4 + 3] = 255.0f;
    }
    if (tid == 0) g_done = 0;   // reset ticket for next replay
}

// ---------------------------------------------------------------------------
extern "C" void kernel_launch(void* const* d_in, const int* in_sizes, int n_in,
                              void* d_out, int out_size) {
    const float* x  = (const float*)d_in[0];
    const float* rc = (const float*)d_in[1];
    const float* gc = (const float*)d_in[2];
    const float* bc = (const float*)d_in[3];
    int n = in_sizes[0] / 4;   // number of pixels

    // size grid to exactly one resident wave (host-side, capture-safe)
    int dev = 0, sms = 148, occ = 5;
    cudaGetDevice(&dev);
    cudaDeviceGetAttribute(&sms, cudaDevAttrMultiProcessorCount, dev);
    cudaOccupancyMaxActiveBlocksPerMultiprocessor(&occ, fused_kernel, TPB, 0);
    if (occ < 1) occ = 1;
    int grid   = sms * occ;
    int stride = grid * TPB;
    int full   = n / stride;

    fused_kernel<<<grid, TPB>>>((const float4*)x, n, full, stride,
                                rc, gc, bc, (float*)d_out);
}